// round 8
// baseline (speedup 1.0000x reference)
#include <cuda_runtime.h>
#include <cuda_bf16.h>
#include <cuda_fp16.h>
#include <cstdint>

static constexpr int NNODES = 100000;
static constexpr int NEDGES = 3200000;
static constexpr int NFEAT  = 512;
static constexpr int NHID   = 256;
static constexpr int SCAN_B = 1024;
static constexpr int NBLK_SCAN = (NNODES + SCAN_B - 1) / SCAN_B;  // 98

// ---- static device scratch (allocation-free per harness rules) ----
__device__ __half         g_sup_h[NNODES * NHID];   // GEMM output fp16 (SpMM gathers)
__device__ float          g_h1[NNODES * NHID];      // layer-1 output (fp32, feeds GEMM2)
__device__ __nv_bfloat16  g_w1hT[NHID * NFEAT];     // W1^T bf16 hi  [N,K]
__device__ __nv_bfloat16  g_w1lT[NHID * NFEAT];     // W1^T bf16 lo
__device__ __nv_bfloat16  g_w2hT[NHID * NHID];      // W2^T bf16 hi  [N,K]
__device__ __nv_bfloat16  g_w2lT[NHID * NHID];      // W2^T bf16 lo
__device__ int    g_rowptr[NNODES + 1];
__device__ int    g_cursor[NNODES];
__device__ int    g_deg[NNODES];
__device__ int    g_bsum[128];
__device__ int2   g_edge[NEDGES];                   // packed {col, val_bits}

// ============================ helpers ============================

__device__ __forceinline__ uint32_t smem_u32(const void* p) {
    uint32_t a;
    asm("{ .reg .u64 t; cvta.to.shared.u64 t, %1; cvt.u32.u64 %0, t; }"
        : "=r"(a) : "l"(p));
    return a;
}

// swizzle for 64-byte rows (8 rows x 64B atom): XOR bits[4:5] with bits[7:8]
__device__ __forceinline__ uint32_t sw64(uint32_t off) {
    return off ^ ((off >> 3) & 0x30);
}

__device__ __forceinline__ uint32_t pack_bf16x2(float a, float b) {
    __nv_bfloat162 t;
    t.x = __float2bfloat16(a);
    t.y = __float2bfloat16(b);
    return *reinterpret_cast<uint32_t*>(&t);
}

__device__ __forceinline__ void ldsm_x4(uint32_t* r, uint32_t addr) {
    asm volatile("ldmatrix.sync.aligned.m8n8.x4.shared.b16 {%0,%1,%2,%3}, [%4];"
        : "=r"(r[0]), "=r"(r[1]), "=r"(r[2]), "=r"(r[3]) : "r"(addr));
}

__device__ __forceinline__ void mma_bf16(float* c, const uint32_t* a,
                                         uint32_t b0, uint32_t b1) {
    asm volatile(
        "mma.sync.aligned.m16n8k16.row.col.f32.bf16.bf16.f32 "
        "{%0,%1,%2,%3}, {%4,%5,%6,%7}, {%8,%9}, {%0,%1,%2,%3};"
        : "+f"(c[0]), "+f"(c[1]), "+f"(c[2]), "+f"(c[3])
        : "r"(a[0]), "r"(a[1]), "r"(a[2]), "r"(a[3]), "r"(b0), "r"(b1));
}

__device__ __forceinline__ void cp_async16(uint32_t smem_addr, const void* gmem) {
    asm volatile("cp.async.ca.shared.global [%0], [%1], 16;"
        :: "r"(smem_addr), "l"(gmem));
}
__device__ __forceinline__ void cp_commit() {
    asm volatile("cp.async.commit_group;");
}
template<int N>
__device__ __forceinline__ void cp_wait() {
    asm volatile("cp.async.wait_group %0;" :: "n"(N));
}

// ============================ CSR construction ============================

__global__ void zero_deg_kernel() {
    int i = blockIdx.x * blockDim.x + threadIdx.x;
    if (i < NNODES) g_deg[i] = 0;
}

__global__ void count_deg_kernel(const int* __restrict__ erow) {
    int e = blockIdx.x * blockDim.x + threadIdx.x;
    if (e < NEDGES) atomicAdd(&g_deg[erow[e]], 1);
}

__global__ void scan1_kernel() {
    __shared__ int s[SCAN_B];
    int tx = threadIdx.x;
    int gid = blockIdx.x * SCAN_B + tx;
    int v = (gid < NNODES) ? g_deg[gid] : 0;
    s[tx] = v;
    __syncthreads();
    for (int off = 1; off < SCAN_B; off <<= 1) {
        int t = (tx >= off) ? s[tx - off] : 0;
        __syncthreads();
        s[tx] += t;
        __syncthreads();
    }
    if (gid < NNODES) g_rowptr[gid + 1] = s[tx];
    if (tx == SCAN_B - 1) g_bsum[blockIdx.x] = s[tx];
}

__global__ void scan2_kernel() {
    __shared__ int s[128];
    int tx = threadIdx.x;
    int v = (tx < NBLK_SCAN) ? g_bsum[tx] : 0;
    s[tx] = v;
    __syncthreads();
    for (int off = 1; off < 128; off <<= 1) {
        int t = (tx >= off) ? s[tx - off] : 0;
        __syncthreads();
        s[tx] += t;
        __syncthreads();
    }
    if (tx < NBLK_SCAN) g_bsum[tx] = s[tx];
}

__global__ void scan3_kernel() {
    int gid = blockIdx.x * SCAN_B + threadIdx.x;
    if (gid < NNODES) {
        int off = blockIdx.x ? g_bsum[blockIdx.x - 1] : 0;
        int v = g_rowptr[gid + 1] + off;
        g_rowptr[gid + 1] = v;
        if (gid + 1 < NNODES) g_cursor[gid + 1] = v;
        if (gid == 0) { g_rowptr[0] = 0; g_cursor[0] = 0; }
    }
}

__global__ void scatter_kernel(const int* __restrict__ erow,
                               const int* __restrict__ ecol,
                               const float* __restrict__ eval) {
    int e = blockIdx.x * blockDim.x + threadIdx.x;
    if (e < NEDGES) {
        int r = erow[e];
        int p = atomicAdd(&g_cursor[r], 1);
        g_edge[p] = make_int2(ecol[e], __float_as_int(eval[e]));
    }
}

// ============================ weight split (transpose + bf16 hi/lo) ============================
// W [K, N] fp32 -> WhT/WlT [N, K] bf16

__global__ void split_w_kernel(const float* __restrict__ W, int K, int Nn,
                               __nv_bfloat16* __restrict__ WhT,
                               __nv_bfloat16* __restrict__ WlT) {
    int idx = blockIdx.x * blockDim.x + threadIdx.x;
    if (idx >= K * Nn) return;
    int k = idx / Nn, n = idx % Nn;
    float x = W[idx];
    __nv_bfloat16 h = __float2bfloat16(x);
    WhT[(size_t)n * K + k] = h;
    WlT[(size_t)n * K + k] = __float2bfloat16(x - __bfloat162float(h));
}

// ============================ bf16-split tensor-core GEMM ============================
// Ch[M,Nn] = fp16( A[M,K] @ B[K,Nn] ), C ~= Ah*Bh + Ah*Bl + Al*Bh (fp32 acc).
// Block tile 128x128, BK=32, 256 threads (8 warps, each 32x64).
// A fp32 -> convert in-kernel (single-buffered SMEM).
// B pre-split bf16 [Nn,K] -> cp.async, double-buffered SMEM.

static constexpr int AH_OFF = 0;
static constexpr int AL_OFF = 8192;
static constexpr int B_OFF  = 16384;          // two 16KB buffers (hi 8KB + lo 8KB each)
static constexpr int B_BUF  = 16384;

__global__ __launch_bounds__(256) void gemm_mma_kernel(
    int M, int Nn, int K,
    const float* __restrict__ A,
    const __nv_bfloat16* __restrict__ BhT, const __nv_bfloat16* __restrict__ BlT,
    __half* __restrict__ Ch)
{
    __shared__ char smem[49152];
    uint32_t sb = smem_u32(smem);

    int tid = threadIdx.x;
    int lane = tid & 31;
    int wid = tid >> 5;
    int wm = wid & 3;          // warp row: 4 x 32 rows
    int wn = wid >> 2;         // warp col: 2 x 64 cols
    int m0 = blockIdx.y * 128;
    int n0 = blockIdx.x * 128;

    int arow = tid & 127;
    int akh  = tid >> 7;                 // 0/1: which 16-k half
    int grow = m0 + arow;
    bool avalid = grow < M;

    uint32_t so1 = sw64((uint32_t)(arow * 64 + akh * 32));
    uint32_t so2 = sw64((uint32_t)(arow * 64 + akh * 32 + 16));

    float aF[16];
    float acc[2][8][4];
#pragma unroll
    for (int i = 0; i < 2; i++)
#pragma unroll
        for (int j = 0; j < 8; j++)
#pragma unroll
            for (int q = 0; q < 4; q++) acc[i][j][q] = 0.f;

    const int NC = K / 32;

    auto stage_b = [&](int ch, int buf) {
        int k0 = ch * 32;
        const __nv_bfloat16* sh = BhT + (size_t)(n0 + arow) * K + k0 + akh * 16;
        const __nv_bfloat16* sl = BlT + (size_t)(n0 + arow) * K + k0 + akh * 16;
        uint32_t bb = sb + B_OFF + buf * B_BUF;
        cp_async16(bb + so1, sh);
        cp_async16(bb + so2, sh + 8);
        cp_async16(bb + 8192 + so1, sl);
        cp_async16(bb + 8192 + so2, sl + 8);
    };

    auto load_a_regs = [&](int ch) {
        int k0 = ch * 32;
        if (avalid) {
            const float* ap = A + (size_t)grow * K + k0 + akh * 16;
#pragma unroll
            for (int g = 0; g < 4; g++) {
                float4 v = *reinterpret_cast<const float4*>(ap + g * 4);
                aF[g * 4 + 0] = v.x; aF[g * 4 + 1] = v.y;
                aF[g * 4 + 2] = v.z; aF[g * 4 + 3] = v.w;
            }
        } else {
#pragma unroll
            for (int j = 0; j < 16; j++) aF[j] = 0.f;
        }
    };

    auto store_a_conv = [&]() {
        uint32_t hi[8], lo[8];
#pragma unroll
        for (int j = 0; j < 8; j++) {
            float x = aF[2 * j], y = aF[2 * j + 1];
            __nv_bfloat16 hx = __float2bfloat16(x);
            __nv_bfloat16 hy = __float2bfloat16(y);
            __nv_bfloat162 hp; hp.x = hx; hp.y = hy;
            hi[j] = *reinterpret_cast<uint32_t*>(&hp);
            lo[j] = pack_bf16x2(x - __bfloat162float(hx), y - __bfloat162float(hy));
        }
        *reinterpret_cast<uint4*>(smem + AH_OFF + so1) =
            make_uint4(hi[0], hi[1], hi[2], hi[3]);
        *reinterpret_cast<uint4*>(smem + AH_OFF + so2) =
            make_uint4(hi[4], hi[5], hi[6], hi[7]);
        *reinterpret_cast<uint4*>(smem + AL_OFF + so1) =
            make_uint4(lo[0], lo[1], lo[2], lo[3]);
        *reinterpret_cast<uint4*>(smem + AL_OFF + so2) =
            make_uint4(lo[4], lo[5], lo[6], lo[7]);
    };

    auto compute = [&](int buf) {
        uint32_t bhbase = sb + B_OFF + buf * B_BUF;
        uint32_t blbase = bhbase + 8192;
        // A fragments for both k-steps
        uint32_t ah[2][2][4], al[2][2][4];   // [s][mt]
#pragma unroll
        for (int s = 0; s < 2; s++) {
            uint32_t roff = (uint32_t)((wm * 32 + (lane & 15)) * 64
                                       + s * 32 + (lane >> 4) * 16);
#pragma unroll
            for (int mt = 0; mt < 2; mt++) {
                uint32_t off = roff + (uint32_t)(mt * 16 * 64);
                ldsm_x4(ah[s][mt], sb + AH_OFF + sw64(off));
                ldsm_x4(al[s][mt], sb + AL_OFF + sw64(off));
            }
        }
        // stream B tiles
        uint32_t broff = (uint32_t)((wn * 64 + (lane & 7)) * 64 + (lane >> 3) * 16);
#pragma unroll
        for (int nt = 0; nt < 8; nt++) {
            uint32_t off = broff + (uint32_t)(nt * 8 * 64);
            uint32_t bh[4], bl[4];
            ldsm_x4(bh, bhbase + sw64(off));
            ldsm_x4(bl, blbase + sw64(off));
#pragma unroll
            for (int s = 0; s < 2; s++)
#pragma unroll
                for (int mt = 0; mt < 2; mt++) {
                    mma_bf16(acc[mt][nt], ah[s][mt], bh[2 * s], bh[2 * s + 1]);
                    mma_bf16(acc[mt][nt], ah[s][mt], bl[2 * s], bl[2 * s + 1]);
                    mma_bf16(acc[mt][nt], al[s][mt], bh[2 * s], bh[2 * s + 1]);
                }
        }
    };

    // ---- prologue ----
    stage_b(0, 0);
    cp_commit();
    load_a_regs(0);

    for (int ch = 0; ch < NC; ch++) {
        int cur = ch & 1, nxt = cur ^ 1;
        bool last = (ch == NC - 1);
        if (!last) {
            stage_b(ch + 1, nxt);      // overlaps with compute(cur)
            cp_commit();
        }
        store_a_conv();
        if (!last) cp_wait<1>(); else cp_wait<0>();
        __syncthreads();
        if (!last) load_a_regs(ch + 1);   // LDG overlaps compute
        compute(cur);
        __syncthreads();
    }

    // ---- epilogue: fp32 acc -> fp16 support ----
#pragma unroll
    for (int mt = 0; mt < 2; mt++) {
        int r0 = m0 + wm * 32 + mt * 16 + (lane >> 2);
        int r1 = r0 + 8;
#pragma unroll
        for (int nt = 0; nt < 8; nt++) {
            int c = n0 + wn * 64 + nt * 8 + (lane & 3) * 2;
            if (r0 < M)
                *reinterpret_cast<__half2*>(Ch + (size_t)r0 * Nn + c) =
                    __floats2half2_rn(acc[mt][nt][0], acc[mt][nt][1]);
            if (r1 < M)
                *reinterpret_cast<__half2*>(Ch + (size_t)r1 * Nn + c) =
                    __floats2half2_rn(acc[mt][nt][2], acc[mt][nt][3]);
        }
    }
}

// ============================ SpMM (fp16 gather) + bias + PReLU ============================
// Warp per row: 32 lanes x 8 fp16 features (16B) = 256 features.

__global__ __launch_bounds__(256) void spmm_bias_prelu_kernel(
    const uint4* __restrict__ sup, const float* __restrict__ bias,
    const float* __restrict__ alpha, float4* __restrict__ out)
{
    int lane = threadIdx.x & 31;
    int wrp  = threadIdx.x >> 5;
    int r = blockIdx.x * 8 + wrp;
    if (r >= NNODES) return;

    int s = g_rowptr[r];
    int e = g_rowptr[r + 1];

    float acc[8];
#pragma unroll
    for (int q = 0; q < 8; q++) acc[q] = 0.f;

    int j = s;
    for (; j + 1 < e; j += 2) {
        int2 E0 = g_edge[j];
        int2 E1 = g_edge[j + 1];
        float v0 = __int_as_float(E0.y);
        float v1 = __int_as_float(E1.y);
        uint4 p0 = sup[(size_t)E0.x * 32 + lane];
        uint4 p1 = sup[(size_t)E1.x * 32 + lane];
        const uint32_t* w0 = &p0.x;
        const uint32_t* w1 = &p1.x;
#pragma unroll
        for (int q = 0; q < 4; q++) {
            float2 f0 = __half22float2(*reinterpret_cast<const __half2*>(&w0[q]));
            float2 f1 = __half22float2(*reinterpret_cast<const __half2*>(&w1[q]));
            acc[2 * q + 0] += v0 * f0.x + v1 * f1.x;
            acc[2 * q + 1] += v0 * f0.y + v1 * f1.y;
        }
    }
    if (j < e) {
        int2 E0 = g_edge[j];
        float v0 = __int_as_float(E0.y);
        uint4 p0 = sup[(size_t)E0.x * 32 + lane];
        const uint32_t* w0 = &p0.x;
#pragma unroll
        for (int q = 0; q < 4; q++) {
            float2 f0 = __half22float2(*reinterpret_cast<const __half2*>(&w0[q]));
            acc[2 * q + 0] += v0 * f0.x;
            acc[2 * q + 1] += v0 * f0.y;
        }
    }

    float a = alpha[0];
    const float4* bp = reinterpret_cast<const float4*>(bias) + lane * 2;
    float4 b0 = bp[0], b1 = bp[1];
    float4 o0, o1;
    o0.x = acc[0] + b0.x; o0.x = o0.x >= 0.f ? o0.x : a * o0.x;
    o0.y = acc[1] + b0.y; o0.y = o0.y >= 0.f ? o0.y : a * o0.y;
    o0.z = acc[2] + b0.z; o0.z = o0.z >= 0.f ? o0.z : a * o0.z;
    o0.w = acc[3] + b0.w; o0.w = o0.w >= 0.f ? o0.w : a * o0.w;
    o1.x = acc[4] + b1.x; o1.x = o1.x >= 0.f ? o1.x : a * o1.x;
    o1.y = acc[5] + b1.y; o1.y = o1.y >= 0.f ? o1.y : a * o1.y;
    o1.z = acc[6] + b1.z; o1.z = o1.z >= 0.f ? o1.z : a * o1.z;
    o1.w = acc[7] + b1.w; o1.w = o1.w >= 0.f ? o1.w : a * o1.w;

    float4* op = out + (size_t)r * 64 + lane * 2;
    op[0] = o0;
    op[1] = o1;
}

// ============================ launch ============================

extern "C" void kernel_launch(void* const* d_in, const int* in_sizes, int n_in,
                              void* d_out, int out_size) {
    const float* x     = (const float*)d_in[0];
    const int*   erow  = (const int*)  d_in[1];
    const int*   ecol  = (const int*)  d_in[2];
    const float* eval  = (const float*)d_in[3];
    const float* W1    = (const float*)d_in[4];
    const float* b1    = (const float*)d_in[5];
    const float* W2    = (const float*)d_in[6];
    const float* b2    = (const float*)d_in[7];
    const float* alpha = (const float*)d_in[8];
    float* out = (float*)d_out;

    __half* suph = nullptr;
    float*  h1   = nullptr;
    __nv_bfloat16 *w1hT = nullptr, *w1lT = nullptr, *w2hT = nullptr, *w2lT = nullptr;
    cudaGetSymbolAddress((void**)&suph, g_sup_h);
    cudaGetSymbolAddress((void**)&h1, g_h1);
    cudaGetSymbolAddress((void**)&w1hT, g_w1hT);
    cudaGetSymbolAddress((void**)&w1lT, g_w1lT);
    cudaGetSymbolAddress((void**)&w2hT, g_w2hT);
    cudaGetSymbolAddress((void**)&w2lT, g_w2lT);

    dim3 gemm_grid(NHID / 128, (NNODES + 127) / 128);
    int spmm_grid = (NNODES + 7) / 8;

    // Order chosen so gemm_mma (layer 1) sits at launch position 3 — the slot
    // ncu captures — while preserving dependencies (CSR only needed by SpMM).
    split_w_kernel<<<(NFEAT * NHID + 255) / 256, 256>>>(W1, NFEAT, NHID, w1hT, w1lT);  // 0
    split_w_kernel<<<(NHID * NHID + 255) / 256, 256>>>(W2, NHID, NHID, w2hT, w2lT);    // 1
    zero_deg_kernel<<<(NNODES + 255) / 256, 256>>>();                                   // 2
    gemm_mma_kernel<<<gemm_grid, 256>>>(NNODES, NHID, NFEAT, x, w1hT, w1lT, suph);      // 3 (captured)
    count_deg_kernel<<<NEDGES / 256, 256>>>(erow);                                      // 4
    scan1_kernel<<<NBLK_SCAN, SCAN_B>>>();                                              // 5
    scan2_kernel<<<1, 128>>>();                                                         // 6
    scan3_kernel<<<NBLK_SCAN, SCAN_B>>>();                                              // 7
    scatter_kernel<<<NEDGES / 256, 256>>>(erow, ecol, eval);                            // 8
    spmm_bias_prelu_kernel<<<spmm_grid, 256>>>((const uint4*)suph, b1, alpha, (float4*)h1);  // 9
    gemm_mma_kernel<<<gemm_grid, 256>>>(NNODES, NHID, NHID, h1, w2hT, w2lT, suph);      // 10
    spmm_bias_prelu_kernel<<<spmm_grid, 256>>>((const uint4*)suph, b2, alpha, (float4*)out); // 11
}

// round 9
// speedup vs baseline: 1.4884x; 1.4884x over previous
#include <cuda_runtime.h>
#include <cuda_bf16.h>
#include <cuda_fp16.h>
#include <cstdint>

static constexpr int NNODES = 100000;
static constexpr int NEDGES = 3200000;
static constexpr int NFEAT  = 512;
static constexpr int NHID   = 256;
static constexpr int SCAN_B = 1024;
static constexpr int NBLK_SCAN = (NNODES + SCAN_B - 1) / SCAN_B;  // 98

// ---- static device scratch (allocation-free per harness rules) ----
__device__ __half g_sup_h[NNODES * NHID];   // GEMM output fp16 (SpMM gathers)
__device__ float  g_h1[NNODES * NHID];      // layer-1 output (fp32, feeds GEMM2)
__device__ int    g_rowptr[NNODES + 1];
__device__ int    g_cursor[NNODES];
__device__ int    g_deg[NNODES];
__device__ int    g_bsum[128];
__device__ int2   g_edge[NEDGES];           // packed {col, val_bits}

// ============================ helpers ============================

__device__ __forceinline__ uint32_t smem_u32(const void* p) {
    uint32_t a;
    asm("{ .reg .u64 t; cvta.to.shared.u64 t, %1; cvt.u32.u64 %0, t; }"
        : "=r"(a) : "l"(p));
    return a;
}

// swizzle for 64-byte rows (8 rows x 64B atom)
__device__ __forceinline__ uint32_t sw64(uint32_t off) {
    return off ^ ((off >> 3) & 0x30);
}

__device__ __forceinline__ uint32_t pack_bf16x2(float a, float b) {
    __nv_bfloat162 t;
    t.x = __float2bfloat16(a);
    t.y = __float2bfloat16(b);
    return *reinterpret_cast<uint32_t*>(&t);
}

__device__ __forceinline__ void ldsm_x4(uint32_t* r, uint32_t addr) {
    asm volatile("ldmatrix.sync.aligned.m8n8.x4.shared.b16 {%0,%1,%2,%3}, [%4];"
        : "=r"(r[0]), "=r"(r[1]), "=r"(r[2]), "=r"(r[3]) : "r"(addr));
}

__device__ __forceinline__ void mma_bf16(float* c, const uint32_t* a,
                                         uint32_t b0, uint32_t b1) {
    asm volatile(
        "mma.sync.aligned.m16n8k16.row.col.f32.bf16.bf16.f32 "
        "{%0,%1,%2,%3}, {%4,%5,%6,%7}, {%8,%9}, {%0,%1,%2,%3};"
        : "+f"(c[0]), "+f"(c[1]), "+f"(c[2]), "+f"(c[3])
        : "r"(a[0]), "r"(a[1]), "r"(a[2]), "r"(a[3]), "r"(b0), "r"(b1));
}

// ============================ CSR construction ============================

__global__ void zero_deg_kernel() {
    int i = blockIdx.x * blockDim.x + threadIdx.x;
    if (i < NNODES) g_deg[i] = 0;
}

__global__ void count_deg_kernel(const int* __restrict__ erow) {
    int e = blockIdx.x * blockDim.x + threadIdx.x;
    if (e < NEDGES) atomicAdd(&g_deg[erow[e]], 1);
}

__global__ void scan1_kernel() {
    __shared__ int s[SCAN_B];
    int tx = threadIdx.x;
    int gid = blockIdx.x * SCAN_B + tx;
    int v = (gid < NNODES) ? g_deg[gid] : 0;
    s[tx] = v;
    __syncthreads();
    for (int off = 1; off < SCAN_B; off <<= 1) {
        int t = (tx >= off) ? s[tx - off] : 0;
        __syncthreads();
        s[tx] += t;
        __syncthreads();
    }
    if (gid < NNODES) g_rowptr[gid + 1] = s[tx];
    if (tx == SCAN_B - 1) g_bsum[blockIdx.x] = s[tx];
}

__global__ void scan2_kernel() {
    __shared__ int s[128];
    int tx = threadIdx.x;
    int v = (tx < NBLK_SCAN) ? g_bsum[tx] : 0;
    s[tx] = v;
    __syncthreads();
    for (int off = 1; off < 128; off <<= 1) {
        int t = (tx >= off) ? s[tx - off] : 0;
        __syncthreads();
        s[tx] += t;
        __syncthreads();
    }
    if (tx < NBLK_SCAN) g_bsum[tx] = s[tx];
}

__global__ void scan3_kernel() {
    int gid = blockIdx.x * SCAN_B + threadIdx.x;
    if (gid < NNODES) {
        int off = blockIdx.x ? g_bsum[blockIdx.x - 1] : 0;
        int v = g_rowptr[gid + 1] + off;
        g_rowptr[gid + 1] = v;
        if (gid + 1 < NNODES) g_cursor[gid + 1] = v;
        if (gid == 0) { g_rowptr[0] = 0; g_cursor[0] = 0; }
    }
}

__global__ void scatter_kernel(const int* __restrict__ erow,
                               const int* __restrict__ ecol,
                               const float* __restrict__ eval) {
    int e = blockIdx.x * blockDim.x + threadIdx.x;
    if (e < NEDGES) {
        int r = erow[e];
        int p = atomicAdd(&g_cursor[r], 1);
        g_edge[p] = make_int2(ecol[e], __float_as_int(eval[e]));
    }
}

// ============================ bf16-split tensor-core GEMM ============================
// Ch[M,Nn] = fp16( A[M,K] @ B[K,Nn] ), C ~= Ah*Bh + Ah*Bl + Al*Bh (fp32 acc).
// Block tile 128x128, BK=32, 256 threads (8 warps, each 32x64).
// A: direct gmem->register fragments (no SMEM, no LDSM), one chunk prefetched.
// B: strided LDG + in-reg convert + STS, double-buffered SMEM (2x16KB).
// One __syncthreads per chunk.

static constexpr int B_BUF = 16384;   // per buffer: hi 8KB + lo 8KB

__global__ __launch_bounds__(256) void gemm_mma_kernel(
    int M, int Nn, int K,
    const float* __restrict__ A, const float* __restrict__ B, __half* __restrict__ Ch)
{
    __shared__ char smem[2 * B_BUF];
    uint32_t sb = smem_u32(smem);

    int tid = threadIdx.x;
    int lane = tid & 31;
    int wid = tid >> 5;
    int wm = wid & 3;          // warp row: 4 x 32 rows
    int wn = wid >> 2;         // warp col: 2 x 64 cols
    int m0 = blockIdx.y * 128;
    int n0 = blockIdx.x * 128;

    // B staging coords (same as R7)
    int brow = tid & 127;               // B^T tile row (= n)
    int bkh  = tid >> 7;                // which 16-k half
    uint32_t bso1 = sw64((uint32_t)(brow * 64 + bkh * 32));
    uint32_t bso2 = sw64((uint32_t)(brow * 64 + bkh * 32 + 16));

    // A fragment row addresses (clamped; rows >= M masked at epilogue)
    int arow0 = wm * 32 + (lane >> 2);              // + mt*16 (+8)
    int acol  = 2 * (lane & 3);                     // + s*16 (+8)
    size_t aoff[2][2];                              // [mt][half] row offsets
#pragma unroll
    for (int mt = 0; mt < 2; mt++) {
        int r0 = m0 + arow0 + mt * 16;
        int r1 = r0 + 8;
        aoff[mt][0] = (size_t)((r0 < M) ? r0 : 0) * K;
        aoff[mt][1] = (size_t)((r1 < M) ? r1 : 0) * K;
    }

    float bF[16];
    float2 pf[2][2][4];        // prefetched A fp32 [mt][s][frag]
    uint32_t ah[2][2][4], al[2][2][4];   // converted A frags [s][mt]
    float acc[2][8][4];
#pragma unroll
    for (int i = 0; i < 2; i++)
#pragma unroll
        for (int j = 0; j < 8; j++)
#pragma unroll
            for (int q = 0; q < 4; q++) acc[i][j][q] = 0.f;

    const int NC = K / 32;

    auto prefetch_a = [&](int ch) {
        int k0 = ch * 32;
#pragma unroll
        for (int mt = 0; mt < 2; mt++)
#pragma unroll
            for (int s = 0; s < 2; s++) {
                int cb = k0 + s * 16 + acol;
                pf[mt][s][0] = *reinterpret_cast<const float2*>(A + aoff[mt][0] + cb);
                pf[mt][s][1] = *reinterpret_cast<const float2*>(A + aoff[mt][1] + cb);
                pf[mt][s][2] = *reinterpret_cast<const float2*>(A + aoff[mt][0] + cb + 8);
                pf[mt][s][3] = *reinterpret_cast<const float2*>(A + aoff[mt][1] + cb + 8);
            }
    };

    auto convert_a = [&]() {
#pragma unroll
        for (int mt = 0; mt < 2; mt++)
#pragma unroll
            for (int s = 0; s < 2; s++)
#pragma unroll
                for (int j = 0; j < 4; j++) {
                    float x = pf[mt][s][j].x, y = pf[mt][s][j].y;
                    __nv_bfloat16 hx = __float2bfloat16(x);
                    __nv_bfloat16 hy = __float2bfloat16(y);
                    __nv_bfloat162 hp; hp.x = hx; hp.y = hy;
                    ah[s][mt][j] = *reinterpret_cast<uint32_t*>(&hp);
                    al[s][mt][j] = pack_bf16x2(x - __bfloat162float(hx),
                                               y - __bfloat162float(hy));
                }
    };

    auto load_bF = [&](int ch) {
        int k0 = ch * 32;
        const float* bp = B + (size_t)(k0 + bkh * 16) * Nn + n0 + brow;
#pragma unroll
        for (int j = 0; j < 16; j++) bF[j] = bp[(size_t)j * Nn];
    };

    auto store_b = [&](int buf) {
        uint32_t hi[8], lo[8];
#pragma unroll
        for (int j = 0; j < 8; j++) {
            float x = bF[2 * j], y = bF[2 * j + 1];
            __nv_bfloat16 hx = __float2bfloat16(x);
            __nv_bfloat16 hy = __float2bfloat16(y);
            __nv_bfloat162 hp; hp.x = hx; hp.y = hy;
            hi[j] = *reinterpret_cast<uint32_t*>(&hp);
            lo[j] = pack_bf16x2(x - __bfloat162float(hx), y - __bfloat162float(hy));
        }
        char* bb = smem + buf * B_BUF;
        *reinterpret_cast<uint4*>(bb + bso1)        = make_uint4(hi[0], hi[1], hi[2], hi[3]);
        *reinterpret_cast<uint4*>(bb + bso2)        = make_uint4(hi[4], hi[5], hi[6], hi[7]);
        *reinterpret_cast<uint4*>(bb + 8192 + bso1) = make_uint4(lo[0], lo[1], lo[2], lo[3]);
        *reinterpret_cast<uint4*>(bb + 8192 + bso2) = make_uint4(lo[4], lo[5], lo[6], lo[7]);
    };

    auto compute = [&](int buf) {
        uint32_t bhbase = sb + buf * B_BUF;
        uint32_t blbase = bhbase + 8192;
        uint32_t broff = (uint32_t)((wn * 64 + (lane & 7)) * 64 + (lane >> 3) * 16);
#pragma unroll
        for (int nt = 0; nt < 8; nt++) {
            uint32_t off = broff + (uint32_t)(nt * 8 * 64);
            uint32_t bh[4], bl[4];
            ldsm_x4(bh, bhbase + sw64(off));
            ldsm_x4(bl, blbase + sw64(off));
#pragma unroll
            for (int s = 0; s < 2; s++)
#pragma unroll
                for (int mt = 0; mt < 2; mt++) {
                    mma_bf16(acc[mt][nt], ah[s][mt], bh[2 * s], bh[2 * s + 1]);
                    mma_bf16(acc[mt][nt], ah[s][mt], bl[2 * s], bl[2 * s + 1]);
                    mma_bf16(acc[mt][nt], al[s][mt], bh[2 * s], bh[2 * s + 1]);
                }
        }
    };

    // ---- prologue ----
    load_bF(0);
    store_b(0);
    prefetch_a(0);
    __syncthreads();

    for (int ch = 0; ch < NC; ch++) {
        int cur = ch & 1, nxt = cur ^ 1;
        bool last = (ch == NC - 1);
        if (!last) load_bF(ch + 1);      // LDG overlaps compute below
        convert_a();                      // frags for chunk ch from pf
        if (!last) prefetch_a(ch + 1);   // LDG overlaps compute below
        compute(cur);
        if (!last) store_b(nxt);         // STS into other buffer
        __syncthreads();
    }

    // ---- epilogue: fp32 acc -> fp16 support ----
#pragma unroll
    for (int mt = 0; mt < 2; mt++) {
        int r0 = m0 + wm * 32 + mt * 16 + (lane >> 2);
        int r1 = r0 + 8;
#pragma unroll
        for (int nt = 0; nt < 8; nt++) {
            int c = n0 + wn * 64 + nt * 8 + (lane & 3) * 2;
            if (r0 < M)
                *reinterpret_cast<__half2*>(Ch + (size_t)r0 * Nn + c) =
                    __floats2half2_rn(acc[mt][nt][0], acc[mt][nt][1]);
            if (r1 < M)
                *reinterpret_cast<__half2*>(Ch + (size_t)r1 * Nn + c) =
                    __floats2half2_rn(acc[mt][nt][2], acc[mt][nt][3]);
        }
    }
}

// ============================ SpMM (fp16 gather) + bias + PReLU ============================
// Warp per row: 32 lanes x 8 fp16 features (16B) = 256 features.

__global__ __launch_bounds__(256) void spmm_bias_prelu_kernel(
    const uint4* __restrict__ sup, const float* __restrict__ bias,
    const float* __restrict__ alpha, float4* __restrict__ out)
{
    int lane = threadIdx.x & 31;
    int wrp  = threadIdx.x >> 5;
    int r = blockIdx.x * 8 + wrp;
    if (r >= NNODES) return;

    int s = g_rowptr[r];
    int e = g_rowptr[r + 1];

    float acc[8];
#pragma unroll
    for (int q = 0; q < 8; q++) acc[q] = 0.f;

    int j = s;
    for (; j + 1 < e; j += 2) {
        int2 E0 = g_edge[j];
        int2 E1 = g_edge[j + 1];
        float v0 = __int_as_float(E0.y);
        float v1 = __int_as_float(E1.y);
        uint4 p0 = sup[(size_t)E0.x * 32 + lane];
        uint4 p1 = sup[(size_t)E1.x * 32 + lane];
        const uint32_t* w0 = &p0.x;
        const uint32_t* w1 = &p1.x;
#pragma unroll
        for (int q = 0; q < 4; q++) {
            float2 f0 = __half22float2(*reinterpret_cast<const __half2*>(&w0[q]));
            float2 f1 = __half22float2(*reinterpret_cast<const __half2*>(&w1[q]));
            acc[2 * q + 0] += v0 * f0.x + v1 * f1.x;
            acc[2 * q + 1] += v0 * f0.y + v1 * f1.y;
        }
    }
    if (j < e) {
        int2 E0 = g_edge[j];
        float v0 = __int_as_float(E0.y);
        uint4 p0 = sup[(size_t)E0.x * 32 + lane];
        const uint32_t* w0 = &p0.x;
#pragma unroll
        for (int q = 0; q < 4; q++) {
            float2 f0 = __half22float2(*reinterpret_cast<const __half2*>(&w0[q]));
            acc[2 * q + 0] += v0 * f0.x;
            acc[2 * q + 1] += v0 * f0.y;
        }
    }

    float a = alpha[0];
    const float4* bp = reinterpret_cast<const float4*>(bias) + lane * 2;
    float4 b0 = bp[0], b1 = bp[1];
    float4 o0, o1;
    o0.x = acc[0] + b0.x; o0.x = o0.x >= 0.f ? o0.x : a * o0.x;
    o0.y = acc[1] + b0.y; o0.y = o0.y >= 0.f ? o0.y : a * o0.y;
    o0.z = acc[2] + b0.z; o0.z = o0.z >= 0.f ? o0.z : a * o0.z;
    o0.w = acc[3] + b0.w; o0.w = o0.w >= 0.f ? o0.w : a * o0.w;
    o1.x = acc[4] + b1.x; o1.x = o1.x >= 0.f ? o1.x : a * o1.x;
    o1.y = acc[5] + b1.y; o1.y = o1.y >= 0.f ? o1.y : a * o1.y;
    o1.z = acc[6] + b1.z; o1.z = o1.z >= 0.f ? o1.z : a * o1.z;
    o1.w = acc[7] + b1.w; o1.w = o1.w >= 0.f ? o1.w : a * o1.w;

    float4* op = out + (size_t)r * 64 + lane * 2;
    op[0] = o0;
    op[1] = o1;
}

// ============================ launch ============================

extern "C" void kernel_launch(void* const* d_in, const int* in_sizes, int n_in,
                              void* d_out, int out_size) {
    const float* x     = (const float*)d_in[0];
    const int*   erow  = (const int*)  d_in[1];
    const int*   ecol  = (const int*)  d_in[2];
    const float* eval  = (const float*)d_in[3];
    const float* W1    = (const float*)d_in[4];
    const float* b1    = (const float*)d_in[5];
    const float* W2    = (const float*)d_in[6];
    const float* b2    = (const float*)d_in[7];
    const float* alpha = (const float*)d_in[8];
    float* out = (float*)d_out;

    __half* suph = nullptr;
    float*  h1   = nullptr;
    cudaGetSymbolAddress((void**)&suph, g_sup_h);
    cudaGetSymbolAddress((void**)&h1, g_h1);

    dim3 gemm_grid(NHID / 128, (NNODES + 127) / 128);
    int spmm_grid = (NNODES + 7) / 8;

    // gemm1 kept at launch index 3 (the slot ncu captures)
    zero_deg_kernel<<<(NNODES + 255) / 256, 256>>>();                                   // 0
    count_deg_kernel<<<NEDGES / 256, 256>>>(erow);                                      // 1
    scan1_kernel<<<NBLK_SCAN, SCAN_B>>>();                                              // 2
    gemm_mma_kernel<<<gemm_grid, 256>>>(NNODES, NHID, NFEAT, x, W1, suph);              // 3 (captured)
    scan2_kernel<<<1, 128>>>();                                                         // 4
    scan3_kernel<<<NBLK_SCAN, SCAN_B>>>();                                              // 5
    scatter_kernel<<<NEDGES / 256, 256>>>(erow, ecol, eval);                            // 6
    spmm_bias_prelu_kernel<<<spmm_grid, 256>>>((const uint4*)suph, b1, alpha, (float4*)h1);  // 7
    gemm_mma_kernel<<<gemm_grid, 256>>>(NNODES, NHID, NHID, h1, W2, suph);              // 8
    spmm_bias_prelu_kernel<<<spmm_grid, 256>>>((const uint4*)suph, b2, alpha, (float4*)out); // 9
}

// round 10
// speedup vs baseline: 1.7058x; 1.1461x over previous
#include <cuda_runtime.h>
#include <cuda_bf16.h>
#include <cuda_fp16.h>
#include <cstdint>

static constexpr int NNODES = 100000;
static constexpr int NEDGES = 3200000;
static constexpr int NFEAT  = 512;
static constexpr int NHID   = 256;
static constexpr int SCAN_B = 1024;
static constexpr int NBLK_SCAN = (NNODES + SCAN_B - 1) / SCAN_B;  // 98

// ---- static device scratch (allocation-free per harness rules) ----
__device__ __half         g_sup_h[NNODES * NHID];    // GEMM out fp16 (SpMM gathers)
__device__ __nv_bfloat16  g_xh[NNODES * NFEAT];      // x split hi
__device__ __nv_bfloat16  g_xl[NNODES * NFEAT];      // x split lo
__device__ __nv_bfloat16  g_h1h[NNODES * NHID];      // h1 split hi
__device__ __nv_bfloat16  g_h1l[NNODES * NHID];      // h1 split lo
__device__ __nv_bfloat16  g_w1hT[NHID * NFEAT];      // W1^T hi [N,K]
__device__ __nv_bfloat16  g_w1lT[NHID * NFEAT];
__device__ __nv_bfloat16  g_w2hT[NHID * NHID];       // W2^T hi [N,K]
__device__ __nv_bfloat16  g_w2lT[NHID * NHID];
__device__ int    g_rowptr[NNODES + 1];
__device__ int    g_cursor[NNODES];
__device__ int    g_deg[NNODES];
__device__ int    g_bsum[128];
__device__ int2   g_edge[NEDGES];                    // packed {col, val_bits}

// ============================ helpers ============================

__device__ __forceinline__ uint32_t smem_u32(const void* p) {
    uint32_t a;
    asm("{ .reg .u64 t; cvta.to.shared.u64 t, %1; cvt.u32.u64 %0, t; }"
        : "=r"(a) : "l"(p));
    return a;
}

// swizzle for 64-byte rows (8 rows x 64B atom)
__device__ __forceinline__ uint32_t sw64(uint32_t off) {
    return off ^ ((off >> 3) & 0x30);
}

__device__ __forceinline__ uint32_t pack_hi2(float a, float b, float& ra, float& rb) {
    __nv_bfloat16 ha = __float2bfloat16(a);
    __nv_bfloat16 hb = __float2bfloat16(b);
    ra = a - __bfloat162float(ha);
    rb = b - __bfloat162float(hb);
    __nv_bfloat162 t; t.x = ha; t.y = hb;
    return *reinterpret_cast<uint32_t*>(&t);
}

__device__ __forceinline__ uint32_t pack_bf16x2(float a, float b) {
    __nv_bfloat162 t;
    t.x = __float2bfloat16(a);
    t.y = __float2bfloat16(b);
    return *reinterpret_cast<uint32_t*>(&t);
}

__device__ __forceinline__ void ldsm_x4(uint32_t* r, uint32_t addr) {
    asm volatile("ldmatrix.sync.aligned.m8n8.x4.shared.b16 {%0,%1,%2,%3}, [%4];"
        : "=r"(r[0]), "=r"(r[1]), "=r"(r[2]), "=r"(r[3]) : "r"(addr));
}

__device__ __forceinline__ void mma_bf16(float* c, const uint32_t* a,
                                         uint32_t b0, uint32_t b1) {
    asm volatile(
        "mma.sync.aligned.m16n8k16.row.col.f32.bf16.bf16.f32 "
        "{%0,%1,%2,%3}, {%4,%5,%6,%7}, {%8,%9}, {%0,%1,%2,%3};"
        : "+f"(c[0]), "+f"(c[1]), "+f"(c[2]), "+f"(c[3])
        : "r"(a[0]), "r"(a[1]), "r"(a[2]), "r"(a[3]), "r"(b0), "r"(b1));
}

__device__ __forceinline__ void cp_async16(uint32_t smem_addr, const void* gmem) {
    asm volatile("cp.async.ca.shared.global [%0], [%1], 16;"
        :: "r"(smem_addr), "l"(gmem));
}
__device__ __forceinline__ void cp_commit() {
    asm volatile("cp.async.commit_group;");
}
template<int N>
__device__ __forceinline__ void cp_wait() {
    asm volatile("cp.async.wait_group %0;" :: "n"(N));
}

// ============================ CSR construction ============================

__global__ void zero_deg_kernel() {
    int i = blockIdx.x * blockDim.x + threadIdx.x;
    if (i < NNODES) g_deg[i] = 0;
}

__global__ void count_deg_kernel(const int* __restrict__ erow) {
    int e = blockIdx.x * blockDim.x + threadIdx.x;
    if (e < NEDGES) atomicAdd(&g_deg[erow[e]], 1);
}

__global__ void scan1_kernel() {
    __shared__ int s[SCAN_B];
    int tx = threadIdx.x;
    int gid = blockIdx.x * SCAN_B + tx;
    int v = (gid < NNODES) ? g_deg[gid] : 0;
    s[tx] = v;
    __syncthreads();
    for (int off = 1; off < SCAN_B; off <<= 1) {
        int t = (tx >= off) ? s[tx - off] : 0;
        __syncthreads();
        s[tx] += t;
        __syncthreads();
    }
    if (gid < NNODES) g_rowptr[gid + 1] = s[tx];
    if (tx == SCAN_B - 1) g_bsum[blockIdx.x] = s[tx];
}

__global__ void scan2_kernel() {
    __shared__ int s[128];
    int tx = threadIdx.x;
    int v = (tx < NBLK_SCAN) ? g_bsum[tx] : 0;
    s[tx] = v;
    __syncthreads();
    for (int off = 1; off < 128; off <<= 1) {
        int t = (tx >= off) ? s[tx - off] : 0;
        __syncthreads();
        s[tx] += t;
        __syncthreads();
    }
    if (tx < NBLK_SCAN) g_bsum[tx] = s[tx];
}

__global__ void scan3_kernel() {
    int gid = blockIdx.x * SCAN_B + threadIdx.x;
    if (gid < NNODES) {
        int off = blockIdx.x ? g_bsum[blockIdx.x - 1] : 0;
        int v = g_rowptr[gid + 1] + off;
        g_rowptr[gid + 1] = v;
        if (gid + 1 < NNODES) g_cursor[gid + 1] = v;
        if (gid == 0) { g_rowptr[0] = 0; g_cursor[0] = 0; }
    }
}

__global__ void scatter_kernel(const int* __restrict__ erow,
                               const int* __restrict__ ecol,
                               const float* __restrict__ eval) {
    int e = blockIdx.x * blockDim.x + threadIdx.x;
    if (e < NEDGES) {
        int r = erow[e];
        int p = atomicAdd(&g_cursor[r], 1);
        g_edge[p] = make_int2(ecol[e], __float_as_int(eval[e]));
    }
}

// ============================ operand splitting ============================

// X [n] fp32 -> Xh/Xl bf16 (same layout), vectorized by 4
__global__ void split_x_kernel(const float4* __restrict__ X,
                               uint2* __restrict__ Xh, uint2* __restrict__ Xl, int n4) {
    int i = blockIdx.x * blockDim.x + threadIdx.x;
    if (i >= n4) return;
    float4 v = X[i];
    float rx, ry, rz, rw;
    uint32_t h0 = pack_hi2(v.x, v.y, rx, ry);
    uint32_t h1 = pack_hi2(v.z, v.w, rz, rw);
    Xh[i] = make_uint2(h0, h1);
    Xl[i] = make_uint2(pack_bf16x2(rx, ry), pack_bf16x2(rz, rw));
}

// W [K, N] fp32 -> WhT/WlT [N, K] bf16
__global__ void split_w_kernel(const float* __restrict__ W, int K, int Nn,
                               __nv_bfloat16* __restrict__ WhT,
                               __nv_bfloat16* __restrict__ WlT) {
    int idx = blockIdx.x * blockDim.x + threadIdx.x;
    if (idx >= K * Nn) return;
    int k = idx / Nn, n = idx % Nn;
    float x = W[idx];
    __nv_bfloat16 h = __float2bfloat16(x);
    WhT[(size_t)n * K + k] = h;
    WlT[(size_t)n * K + k] = __float2bfloat16(x - __bfloat162float(h));
}

// ============================ bf16-split tensor-core GEMM ============================
// Ch[M,Nn] = fp16( A[M,K] @ B[K,Nn] ), C ~= Ah*Bh + Ah*Bl + Al*Bh (fp32 acc).
// All operands pre-split bf16: A [M,K] hi/lo, B^T [Nn,K] hi/lo.
// Block tile 128x64, BK=32, 256 threads, 8 warps (each 32x32).
// 3-stage cp.async pipeline, one __syncthreads per chunk, 2 CTAs/SM.

static constexpr int ST_AH = 0;
static constexpr int ST_AL = 8192;
static constexpr int ST_BH = 16384;
static constexpr int ST_BL = 20480;
static constexpr int STAGE_BYTES = 24576;
static constexpr int NSTAGES = 3;
static constexpr int GEMM_SMEM = NSTAGES * STAGE_BYTES;   // 73728

__global__ __launch_bounds__(256, 2) void gemm_split_kernel(
    int M, int Nn, int K,
    const __nv_bfloat16* __restrict__ Ah, const __nv_bfloat16* __restrict__ Al,
    const __nv_bfloat16* __restrict__ BhT, const __nv_bfloat16* __restrict__ BlT,
    __half* __restrict__ Ch)
{
    extern __shared__ char smem[];
    uint32_t sb = smem_u32(smem);

    int tid = threadIdx.x;
    int lane = tid & 31;
    int wid = tid >> 5;
    int wm = wid & 3;          // 4 x 32 rows
    int wn = wid >> 2;         // 2 x 32 cols
    int m0 = blockIdx.x * 128; // m on x so consecutive CTAs (y fastest? no: x fastest)
    int n0 = blockIdx.y * 64;

    // NOTE: grid = (ceil(M/128), Nn/64): blockIdx.x fastest -> consecutive CTAs
    // cover different m with same n. We want same-A-reuse concurrent: swap roles:
    // (handled at launch: grid.x = Nn/64, grid.y = m blocks)
    m0 = blockIdx.y * 128;
    n0 = blockIdx.x * 64;

    // ---- staging coords ----
    int arow = tid >> 2;                 // 0..63 (second half at +64)
    int ac16 = tid & 3;                  // 16B chunk within 64B row
    int ar0 = m0 + arow, ar1 = ar0 + 64;
    size_t asrc0 = (size_t)((ar0 < M) ? ar0 : 0) * K + ac16 * 8;
    size_t asrc1 = (size_t)((ar1 < M) ? ar1 : 0) * K + ac16 * 8;
    uint32_t adst0 = sw64((uint32_t)(arow * 64 + ac16 * 16));
    uint32_t adst1 = sw64((uint32_t)((arow + 64) * 64 + ac16 * 16));
    size_t bsrc = (size_t)(n0 + arow) * K + ac16 * 8;    // brow = arow (0..63)
    uint32_t bdst = adst0;

    float acc[2][4][4];
#pragma unroll
    for (int i = 0; i < 2; i++)
#pragma unroll
        for (int j = 0; j < 4; j++)
#pragma unroll
            for (int q = 0; q < 4; q++) acc[i][j][q] = 0.f;

    const int NC = K / 32;

    auto stage = [&](int ch, int buf) {
        int k0 = ch * 32;
        uint32_t st = sb + buf * STAGE_BYTES;
        cp_async16(st + ST_AH + adst0, Ah + asrc0 + k0);
        cp_async16(st + ST_AH + adst1, Ah + asrc1 + k0);
        cp_async16(st + ST_AL + adst0, Al + asrc0 + k0);
        cp_async16(st + ST_AL + adst1, Al + asrc1 + k0);
        cp_async16(st + ST_BH + bdst, BhT + bsrc + k0);
        cp_async16(st + ST_BL + bdst, BlT + bsrc + k0);
    };

    auto compute = [&](int buf) {
        uint32_t st = sb + buf * STAGE_BYTES;
        // A fragments: [s][mt]
        uint32_t ah[2][2][4], al[2][2][4];
#pragma unroll
        for (int s = 0; s < 2; s++) {
            uint32_t roff = (uint32_t)((wm * 32 + (lane & 15)) * 64
                                       + s * 32 + (lane >> 4) * 16);
#pragma unroll
            for (int mt = 0; mt < 2; mt++) {
                uint32_t off = roff + (uint32_t)(mt * 16 * 64);
                ldsm_x4(ah[s][mt], st + ST_AH + sw64(off));
                ldsm_x4(al[s][mt], st + ST_AL + sw64(off));
            }
        }
        uint32_t bro = (uint32_t)((wn * 32 + (lane & 7)) * 64 + (lane >> 3) * 16);
#pragma unroll
        for (int nt = 0; nt < 4; nt++) {
            uint32_t off = bro + (uint32_t)(nt * 8 * 64);
            uint32_t bh[4], bl[4];
            ldsm_x4(bh, st + ST_BH + sw64(off));
            ldsm_x4(bl, st + ST_BL + sw64(off));
#pragma unroll
            for (int s = 0; s < 2; s++)
#pragma unroll
                for (int mt = 0; mt < 2; mt++) {
                    mma_bf16(acc[mt][nt], ah[s][mt], bh[2 * s], bh[2 * s + 1]);
                    mma_bf16(acc[mt][nt], ah[s][mt], bl[2 * s], bl[2 * s + 1]);
                    mma_bf16(acc[mt][nt], al[s][mt], bh[2 * s], bh[2 * s + 1]);
                }
        }
    };

    // ---- 3-stage pipeline ----
    stage(0, 0); cp_commit();
    stage(1, 1); cp_commit();

    for (int ch = 0; ch < NC; ch++) {
        if (ch == NC - 1) cp_wait<0>(); else cp_wait<1>();
        __syncthreads();
        compute(ch % NSTAGES);
        if (ch + 2 < NC) {
            stage(ch + 2, (ch + 2) % NSTAGES);
            cp_commit();
        }
    }

    // ---- epilogue: fp32 acc -> fp16 ----
#pragma unroll
    for (int mt = 0; mt < 2; mt++) {
        int r0 = m0 + wm * 32 + mt * 16 + (lane >> 2);
        int r1 = r0 + 8;
#pragma unroll
        for (int nt = 0; nt < 4; nt++) {
            int c = n0 + wn * 32 + nt * 8 + (lane & 3) * 2;
            if (r0 < M)
                *reinterpret_cast<__half2*>(Ch + (size_t)r0 * Nn + c) =
                    __floats2half2_rn(acc[mt][nt][0], acc[mt][nt][1]);
            if (r1 < M)
                *reinterpret_cast<__half2*>(Ch + (size_t)r1 * Nn + c) =
                    __floats2half2_rn(acc[mt][nt][2], acc[mt][nt][3]);
        }
    }
}

// ============================ SpMM (fp16 gather) + bias + PReLU ============================
// Warp per row: 32 lanes x 8 fp16 features (16B) = 256 features.
// SPLIT_OUT=true: write bf16 hi/lo (feeds GEMM2). false: write fp32 (final out).

template<bool SPLIT_OUT>
__global__ __launch_bounds__(256) void spmm_bias_prelu_kernel(
    const uint4* __restrict__ sup, const float* __restrict__ bias,
    const float* __restrict__ alpha, float4* __restrict__ outF,
    uint4* __restrict__ outH, uint4* __restrict__ outL)
{
    int lane = threadIdx.x & 31;
    int wrp  = threadIdx.x >> 5;
    int r = blockIdx.x * 8 + wrp;
    if (r >= NNODES) return;

    int s = g_rowptr[r];
    int e = g_rowptr[r + 1];

    float acc[8];
#pragma unroll
    for (int q = 0; q < 8; q++) acc[q] = 0.f;

    int j = s;
    for (; j + 1 < e; j += 2) {
        int2 E0 = g_edge[j];
        int2 E1 = g_edge[j + 1];
        float v0 = __int_as_float(E0.y);
        float v1 = __int_as_float(E1.y);
        uint4 p0 = sup[(size_t)E0.x * 32 + lane];
        uint4 p1 = sup[(size_t)E1.x * 32 + lane];
        const uint32_t* w0 = &p0.x;
        const uint32_t* w1 = &p1.x;
#pragma unroll
        for (int q = 0; q < 4; q++) {
            float2 f0 = __half22float2(*reinterpret_cast<const __half2*>(&w0[q]));
            float2 f1 = __half22float2(*reinterpret_cast<const __half2*>(&w1[q]));
            acc[2 * q + 0] += v0 * f0.x + v1 * f1.x;
            acc[2 * q + 1] += v0 * f0.y + v1 * f1.y;
        }
    }
    if (j < e) {
        int2 E0 = g_edge[j];
        float v0 = __int_as_float(E0.y);
        uint4 p0 = sup[(size_t)E0.x * 32 + lane];
        const uint32_t* w0 = &p0.x;
#pragma unroll
        for (int q = 0; q < 4; q++) {
            float2 f0 = __half22float2(*reinterpret_cast<const __half2*>(&w0[q]));
            acc[2 * q + 0] += v0 * f0.x;
            acc[2 * q + 1] += v0 * f0.y;
        }
    }

    float a = alpha[0];
    const float4* bp = reinterpret_cast<const float4*>(bias) + lane * 2;
    float4 b0 = bp[0], b1 = bp[1];
    float o[8];
    o[0] = acc[0] + b0.x; o[1] = acc[1] + b0.y;
    o[2] = acc[2] + b0.z; o[3] = acc[3] + b0.w;
    o[4] = acc[4] + b1.x; o[5] = acc[5] + b1.y;
    o[6] = acc[6] + b1.z; o[7] = acc[7] + b1.w;
#pragma unroll
    for (int q = 0; q < 8; q++) o[q] = o[q] >= 0.f ? o[q] : a * o[q];

    if (SPLIT_OUT) {
        float rr[8];
        uint4 hv, lv;
        hv.x = pack_hi2(o[0], o[1], rr[0], rr[1]);
        hv.y = pack_hi2(o[2], o[3], rr[2], rr[3]);
        hv.z = pack_hi2(o[4], o[5], rr[4], rr[5]);
        hv.w = pack_hi2(o[6], o[7], rr[6], rr[7]);
        lv.x = pack_bf16x2(rr[0], rr[1]);
        lv.y = pack_bf16x2(rr[2], rr[3]);
        lv.z = pack_bf16x2(rr[4], rr[5]);
        lv.w = pack_bf16x2(rr[6], rr[7]);
        outH[(size_t)r * 32 + lane] = hv;
        outL[(size_t)r * 32 + lane] = lv;
    } else {
        float4* op = outF + (size_t)r * 64 + lane * 2;
        op[0] = make_float4(o[0], o[1], o[2], o[3]);
        op[1] = make_float4(o[4], o[5], o[6], o[7]);
    }
}

// ============================ launch ============================

extern "C" void kernel_launch(void* const* d_in, const int* in_sizes, int n_in,
                              void* d_out, int out_size) {
    const float* x     = (const float*)d_in[0];
    const int*   erow  = (const int*)  d_in[1];
    const int*   ecol  = (const int*)  d_in[2];
    const float* eval  = (const float*)d_in[3];
    const float* W1    = (const float*)d_in[4];
    const float* b1    = (const float*)d_in[5];
    const float* W2    = (const float*)d_in[6];
    const float* b2    = (const float*)d_in[7];
    const float* alpha = (const float*)d_in[8];
    float* out = (float*)d_out;

    __half* suph = nullptr;
    __nv_bfloat16 *xh = nullptr, *xl = nullptr, *h1h = nullptr, *h1l = nullptr;
    __nv_bfloat16 *w1hT = nullptr, *w1lT = nullptr, *w2hT = nullptr, *w2lT = nullptr;
    cudaGetSymbolAddress((void**)&suph, g_sup_h);
    cudaGetSymbolAddress((void**)&xh, g_xh);
    cudaGetSymbolAddress((void**)&xl, g_xl);
    cudaGetSymbolAddress((void**)&h1h, g_h1h);
    cudaGetSymbolAddress((void**)&h1l, g_h1l);
    cudaGetSymbolAddress((void**)&w1hT, g_w1hT);
    cudaGetSymbolAddress((void**)&w1lT, g_w1lT);
    cudaGetSymbolAddress((void**)&w2hT, g_w2hT);
    cudaGetSymbolAddress((void**)&w2lT, g_w2lT);

    cudaFuncSetAttribute(gemm_split_kernel,
                         cudaFuncAttributeMaxDynamicSharedMemorySize, GEMM_SMEM);

    dim3 gemm1_grid(NHID / 64, (NNODES + 127) / 128);   // x = n (fastest) -> A L2 reuse
    int spmm_grid = (NNODES + 7) / 8;
    int n4 = NNODES * NFEAT / 4;

    split_w_kernel<<<(NFEAT * NHID + 255) / 256, 256>>>(W1, NFEAT, NHID, w1hT, w1lT);   // 0
    split_w_kernel<<<(NHID * NHID + 255) / 256, 256>>>(W2, NHID, NHID, w2hT, w2lT);     // 1
    split_x_kernel<<<(n4 + 255) / 256, 256>>>((const float4*)x, (uint2*)xh, (uint2*)xl, n4); // 2
    gemm_split_kernel<<<gemm1_grid, 256, GEMM_SMEM>>>(
        NNODES, NHID, NFEAT, xh, xl, w1hT, w1lT, suph);                                 // 3 (captured)
    zero_deg_kernel<<<(NNODES + 255) / 256, 256>>>();                                   // 4
    count_deg_kernel<<<NEDGES / 256, 256>>>(erow);                                      // 5
    scan1_kernel<<<NBLK_SCAN, SCAN_B>>>();                                              // 6
    scan2_kernel<<<1, 128>>>();                                                         // 7
    scan3_kernel<<<NBLK_SCAN, SCAN_B>>>();                                              // 8
    scatter_kernel<<<NEDGES / 256, 256>>>(erow, ecol, eval);                            // 9
    spmm_bias_prelu_kernel<true><<<spmm_grid, 256>>>(
        (const uint4*)suph, b1, alpha, nullptr, (uint4*)h1h, (uint4*)h1l);              // 10
    gemm_split_kernel<<<gemm1_grid, 256, GEMM_SMEM>>>(
        NNODES, NHID, NHID, h1h, h1l, w2hT, w2lT, suph);                                // 11
    spmm_bias_prelu_kernel<false><<<spmm_grid, 256>>>(
        (const uint4*)suph, b2, alpha, (float4*)out, nullptr, nullptr);                 // 12
}